// round 16
// baseline (speedup 1.0000x reference)
#include <cuda_runtime.h>

#define B_ 256
#define T_ 512
#define D_ 128
#define U_ 128
#define C_ 64

typedef unsigned long long ull;

// W1 pair-interleaved over k, built by k0: g_W1P[kp*128+c] = (W1[2kp][c], W1[2kp+1][c])
__device__ float2 g_W1P[64 * 128];

__device__ __forceinline__ ull pk2(float x, float y) {
    ull r; asm("mov.b64 %0, {%1,%2};" : "=l"(r) : "f"(x), "f"(y)); return r;
}
__device__ __forceinline__ void upk2(ull v, float& x, float& y) {
    asm("mov.b64 {%0,%1}, %2;" : "=f"(x), "=f"(y) : "l"(v));
}
__device__ __forceinline__ ull ffma2(ull a, ull b, ull c) {
    ull d; asm("fma.rn.f32x2 %0, %1, %2, %3;" : "=l"(d) : "l"(a), "l"(b), "l"(c)); return d;
}
__device__ __forceinline__ float tanh_fast(float x) {
    float y; asm("tanh.approx.f32 %0, %1;" : "=f"(y) : "f"(x)); return y;
}

// ---------------------------------------------------------------------------
// K0: interleave W1 into g_W1P (runs in ~3us).
// ---------------------------------------------------------------------------
__global__ void k0_prep(const float* __restrict__ W1)
{
    int idx = blockIdx.x * 256 + threadIdx.x;     // 0..8191
    int kp = idx >> 7, c = idx & 127;
    g_W1P[idx] = make_float2(W1[(size_t)(2*kp)   * 128 + c],
                             W1[(size_t)(2*kp+1) * 128 + c]);
}

// ---------------------------------------------------------------------------
// FUSED kernel: one CTA per chain, 256 CTAs, 192 thr, 2 CTAs/SM.
// Rec role (128 thr): recurrence as R15 (W2[:,j] regs, bar.sync 1,128/step,
//   pre-bar h prefetch), h from smem hbuf, y into 32-deep ring.
// Head role (64 thr): per block boundary i:
//   H-GEMM blk i+1 = tanh(X@W1+b1) from xbuf -> hbuf (W1 via g_W1P, L1;
//   two 4r x 4c passes, 16-ull accs), stage X blk i+2 -> xbuf,
//   out-GEMM blk i-1 from ring -> out.
// head_lo alternation: even (bid>>2) CTAs put head on warps 4,5; odd on 2,3.
// ---------------------------------------------------------------------------
#define ST_ROW 136   // 544B = 34x16; halves at float offsets 0 and 68
// smem float offsets
#define SM_WCP   0                       // float2[64][64] = 32KB
#define SM_HIST  8192                    // 32*136 = 17.4KB
#define SM_HBUF  12544                   // 2*2048 = 16KB
#define SM_XBUF  16640                   // 2*2048 = 16KB
#define SM_TOTF  20736                   // 82944 B/CTA -> 2 CTAs/SM

__global__ void __launch_bounds__(192, 2)
k_fused(const float* __restrict__ X,  const float* __restrict__ b1,
        const float* __restrict__ W2, const float* __restrict__ b2,
        const float* __restrict__ Wc, const float* __restrict__ bc,
        float* __restrict__ out)
{
    extern __shared__ float sm[];
    float2* WcP  = (float2*)(sm + SM_WCP);
    float*  hist = sm + SM_HIST;
    float*  hbuf = sm + SM_HBUF;
    float*  xbuf = sm + SM_XBUF;

    const int tid = threadIdx.x;
    const int b   = blockIdx.x;
    const float* Xc = X + (size_t)b * (T_*128);

    const int  head_lo = (b >> 2) & 1;
    const bool is_head = head_lo ? (tid >= 64 && tid < 128) : (tid >= 128);

    // stage Wc pair-interleaved + X block 0 -> xbuf[0] (all threads)
    for (int idx = tid; idx < 4096; idx += 192) {
        int kp = idx >> 6, c = idx & 63;
        WcP[idx] = make_float2(__ldg(Wc + (size_t)(2*kp)   * 64 + c),
                               __ldg(Wc + (size_t)(2*kp+1) * 64 + c));
    }
    for (int idx = tid; idx < 512; idx += 192)
        *(float4*)(xbuf + idx*4) = *(const float4*)(Xc + idx*4);

    if (!is_head) {
        // ========================= RECURRENCE ROLE =========================
        const int j = head_lo ? (tid < 64 ? tid : tid - 64) : tid;

        ull w[64];
        #pragma unroll
        for (int p = 0; p < 64; p++)
            w[p] = pk2(__ldg(W2 + (size_t)(2*p)*128 + j),
                       __ldg(W2 + (size_t)(2*p+1)*128 + j));
        const float b2v = __ldg(b2 + j);

        const int sidx = (j & 63) + (j >> 6) * 68;
        hist[31 * ST_ROW + sidx] = 0.0f;      // y_{-1}
        __syncthreads();                      // P1
        __syncthreads();                      // P2 (head built H blk0)

        #pragma unroll 1
        for (int i = 0; i <= 32; i++) {
            if (i < 32) {
                const int t0 = i * 16;
                const float* hb = hbuf + (i & 1) * 2048;
                float hv = hb[j];
                #pragma unroll 4
                for (int u = 0; u < 16; u++) {
                    const int t = t0 + u;
                    const float* sb = hist + (((t + 31) & 31) * ST_ROW);
                    ull a0 = 0ULL, a1 = 0ULL, a2 = 0ULL, a3 = 0ULL;
                    #pragma unroll
                    for (int p = 0; p < 8; p++) {
                        ulonglong2 s0  = *(const ulonglong2*)(sb + 8*p);
                        ulonglong2 s1  = *(const ulonglong2*)(sb + 68 + 8*p);
                        a0 = ffma2(s0.x,  w[4*p+0],  a0);
                        a1 = ffma2(s0.y,  w[4*p+1],  a1);
                        a2 = ffma2(s1.x,  w[32+4*p], a2);
                        a3 = ffma2(s1.y,  w[33+4*p], a3);
                        ulonglong2 s0b = *(const ulonglong2*)(sb + 8*p + 4);
                        ulonglong2 s1b = *(const ulonglong2*)(sb + 68 + 8*p + 4);
                        a0 = ffma2(s0b.x, w[4*p+2],  a0);
                        a1 = ffma2(s0b.y, w[4*p+3],  a1);
                        a2 = ffma2(s1b.x, w[34+4*p], a2);
                        a3 = ffma2(s1b.y, w[35+4*p], a3);
                    }
                    float x0,y0,x1,y1,x2,y2,x3,y3;
                    upk2(a0,x0,y0); upk2(a1,x1,y1);
                    upk2(a2,x2,y2); upk2(a3,x3,y3);
                    float s = ((x0+y0)+(x1+y1)) + ((x2+y2)+(x3+y3)) + b2v;
                    float yv = hv + tanh_fast(s);
                    if (u < 15) hv = hb[(u + 1) * 128 + j];   // pre-bar prefetch
                    hist[(t & 31) * ST_ROW + sidx] = yv;
                    asm volatile("bar.sync 1, 128;" ::: "memory");
                }
            }
            __syncthreads();                  // block boundary
        }
    } else {
        // ============================ HEAD ROLE ============================
        const int h   = head_lo ? (tid - 64) : (tid - 128);   // 0..63
        const int hr  = (h >> 4) * 4;         // H rows (4 of 16)
        const int hc8 = (h & 15) * 8;         // H col-base (8 of 128)
        const int r0  = (h >> 4) * 4;         // out rows
        const int c4  = (h & 15) * 4;         // out cols

        float bb1[8], bbc[4];
        #pragma unroll
        for (int c = 0; c < 8; c++) bb1[c] = __ldg(b1 + hc8 + c);
        #pragma unroll
        for (int c = 0; c < 4; c++) bbc[c] = __ldg(bc + c4 + c);

        // H-GEMM for block blk: xbuf[blk&1] @ W1 -> hbuf[blk&1], two 4x4 passes
        auto h_gemm = [&](int blk) {
            const float* xs = xbuf + (blk & 1) * 2048;
            float*       hd = hbuf + (blk & 1) * 2048;
            #pragma unroll
            for (int pass = 0; pass < 2; pass++) {
                const int cb = hc8 + pass * 4;
                const float2* wp = g_W1P + cb;
                ull A[4][2];
                #pragma unroll
                for (int r = 0; r < 4; r++) { A[r][0] = 0ULL; A[r][1] = 0ULL; }
                #pragma unroll 4
                for (int kp = 0; kp < 64; kp++) {
                    ulonglong2 wv = *(const ulonglong2*)(wp + (size_t)kp*128);
                    ulonglong2 wu = *(const ulonglong2*)(wp + (size_t)kp*128 + 2);
                    #pragma unroll
                    for (int r = 0; r < 4; r++) {
                        ull xv = *(const ull*)(xs + (hr + r)*128 + 2*kp);
                        A[r][0] = ffma2(xv, wv.x, A[r][0]);
                        A[r][1] = ffma2(xv, wv.y, A[r][1]);
                        // wu holds cols cb+2, cb+3
                        A[r][0] = A[r][0]; // keep pairing below
                    }
                    #pragma unroll
                    for (int r = 0; r < 4; r++) {
                        ull xv = *(const ull*)(xs + (hr + r)*128 + 2*kp);
                        A[r][0] = A[r][0];
                        (void)xv;
                    }
                    // NOTE: cols cb..cb+3 need 4 accumulators; restructure:
                    (void)wu;
                }
                // --- proper 4-col pass (rewritten below) ---
                (void)wp; (void)hd; (void)cb;
            }
            // The lambda above is replaced by the explicit implementation:
            #pragma unroll
            for (int pass = 0; pass < 2; pass++) {
                const int cb = hc8 + pass * 4;
                const float2* wp = g_W1P + cb;
                ull A0[4], A1[4], A2[4], A3[4];
                #pragma unroll
                for (int r = 0; r < 4; r++) { A0[r]=0; A1[r]=0; A2[r]=0; A3[r]=0; }
                #pragma unroll 4
                for (int kp = 0; kp < 64; kp++) {
                    ulonglong2 wv = *(const ulonglong2*)(wp + (size_t)kp*128);
                    ulonglong2 wu = *(const ulonglong2*)(wp + (size_t)kp*128 + 2);
                    #pragma unroll
                    for (int r = 0; r < 4; r++) {
                        ull xv = *(const ull*)(xs + (hr + r)*128 + 2*kp);
                        A0[r] = ffma2(xv, wv.x, A0[r]);
                        A1[r] = ffma2(xv, wv.y, A1[r]);
                        A2[r] = ffma2(xv, wu.x, A2[r]);
                        A3[r] = ffma2(xv, wu.y, A3[r]);
                    }
                }
                #pragma unroll
                for (int r = 0; r < 4; r++) {
                    float4 o; float x, y;
                    upk2(A0[r], x, y); o.x = tanh_fast(x + y + bb1[pass*4+0]);
                    upk2(A1[r], x, y); o.y = tanh_fast(x + y + bb1[pass*4+1]);
                    upk2(A2[r], x, y); o.z = tanh_fast(x + y + bb1[pass*4+2]);
                    upk2(A3[r], x, y); o.w = tanh_fast(x + y + bb1[pass*4+3]);
                    *(float4*)(hd + (hr + r)*128 + cb) = o;
                }
            }
        };

        __syncthreads();                      // P1
        h_gemm(0);                            // H blk0 -> hbuf[0]
        #pragma unroll
        for (int kq = 0; kq < 8; kq++) {      // stage X blk1 -> xbuf[1]
            int idx = h + 64 * kq;
            *(float4*)(xbuf + 2048 + idx*4) = *(const float4*)(Xc + 2048 + idx*4);
        }
        __syncthreads();                      // P2

        #pragma unroll 1
        for (int i = 0; i <= 32; i++) {
            if (i + 1 < 32) h_gemm(i + 1);

            if (i + 2 < 32) {
                const float* src = Xc + (size_t)(i + 2) * 2048;
                float*       dst = xbuf + (i & 1) * 2048;
                #pragma unroll
                for (int kq = 0; kq < 8; kq++) {
                    int idx = h + 64 * kq;
                    *(float4*)(dst + idx*4) = *(const float4*)(src + idx*4);
                }
            }

            if (i >= 1) {
                const int t0h = (i - 1) * 16;
                const float* yr[4];
                #pragma unroll
                for (int r = 0; r < 4; r++)
                    yr[r] = hist + (((t0h + r0 + r) & 31) * ST_ROW);

                ull acc[4][4];
                #pragma unroll
                for (int r = 0; r < 4; r++)
                    #pragma unroll
                    for (int c = 0; c < 4; c++) acc[r][c] = 0ULL;

                #pragma unroll 4
                for (int kp = 0; kp < 32; kp++) {
                    ulonglong2 wc0 = *(const ulonglong2*)(WcP + kp*64 + c4);
                    ulonglong2 wc1 = *(const ulonglong2*)(WcP + kp*64 + c4 + 2);
                    #pragma unroll
                    for (int r = 0; r < 4; r++) {
                        ull yv = *(const ull*)(yr[r] + 2*kp);
                        acc[r][0] = ffma2(yv, wc0.x, acc[r][0]);
                        acc[r][1] = ffma2(yv, wc0.y, acc[r][1]);
                        acc[r][2] = ffma2(yv, wc1.x, acc[r][2]);
                        acc[r][3] = ffma2(yv, wc1.y, acc[r][3]);
                    }
                }
                #pragma unroll 4
                for (int kp = 32; kp < 64; kp++) {
                    ulonglong2 wc0 = *(const ulonglong2*)(WcP + kp*64 + c4);
                    ulonglong2 wc1 = *(const ulonglong2*)(WcP + kp*64 + c4 + 2);
                    #pragma unroll
                    for (int r = 0; r < 4; r++) {
                        ull yv = *(const ull*)(yr[r] + 68 + 2*(kp - 32));
                        acc[r][0] = ffma2(yv, wc0.x, acc[r][0]);
                        acc[r][1] = ffma2(yv, wc0.y, acc[r][1]);
                        acc[r][2] = ffma2(yv, wc1.x, acc[r][2]);
                        acc[r][3] = ffma2(yv, wc1.y, acc[r][3]);
                    }
                }

                #pragma unroll
                for (int r = 0; r < 4; r++) {
                    float4 o; float x, y;
                    upk2(acc[r][0], x, y); o.x = x + y + bbc[0];
                    upk2(acc[r][1], x, y); o.y = x + y + bbc[1];
                    upk2(acc[r][2], x, y); o.z = x + y + bbc[2];
                    upk2(acc[r][3], x, y); o.w = x + y + bbc[3];
                    *(float4*)(out + ((size_t)b * T_ + t0h + r0 + r) * 64 + c4) = o;
                }
            }
            __syncthreads();                  // block boundary
        }
    }
}

extern "C" void kernel_launch(void* const* d_in, const int* in_sizes, int n_in,
                              void* d_out, int out_size) {
    (void)in_sizes; (void)n_in; (void)out_size;
    const float* X  = (const float*)d_in[0];
    const float* W1 = (const float*)d_in[1];
    const float* b1 = (const float*)d_in[2];
    const float* W2 = (const float*)d_in[3];
    const float* b2 = (const float*)d_in[4];
    const float* Wc = (const float*)d_in[5];
    const float* bc = (const float*)d_in[6];
    float* out = (float*)d_out;

    cudaFuncSetAttribute(k_fused, cudaFuncAttributeMaxDynamicSharedMemorySize,
                         SM_TOTF * 4);

    k0_prep<<<32, 256>>>(W1);
    k_fused<<<B_, 192, SM_TOTF * 4>>>(X, b1, W2, b2, Wc, bc, out);
}